// round 4
// baseline (speedup 1.0000x reference)
#include <cuda_runtime.h>
#include <stdint.h>
#include <math.h>

// Problem dims (dataset): N=100000 nodes, C=32 classes, E=3.2M edges
#define NMAX 100000
#define CC 32

// Scratch (device globals, zero-initialized at load; all state is
// self-resetting so repeated graph replays are deterministic).
__device__ float g_p[NMAX * CC];      // softmax probs, valid for UNMASKED nodes only
__device__ float g_s[NMAX * CC];      // scatter matrix; nonzero only on unmasked nodes
__device__ int2  g_info[NMAX];        // .x = bitcast(dinv), .y = label (-1 unmasked)
__device__ float g_deg[NMAX];         // invariant: ==0 at entry of each call
__device__ float g_H[CC * CC];        // ==0 at entry (final kernel resets)
__device__ float g_cnt[CC];           // ==0 at entry
__device__ float g_diag[CC];          // ==0 at entry; masked self-loop dinv^2 per class
__device__ int   g_maskmode;          // 0=uint8, 1=float32, 2=int32

__device__ __forceinline__ bool get_mask(const void* m, int r, int mm) {
    if (mm == 0) return ((const uint8_t*)m)[r] != 0;
    if (mm == 2) return ((const int*)m)[r] != 0;
    return ((const float*)m)[r] != 0.0f;
}

// ---------------------------------------------------------------------------
// deg += segment_sum(w, row) (g_deg pre-zeroed by invariant); self-loop "+1"
// is applied analytically in node_kernel. Block 0 also detects mask dtype
// (a byte-mask viewed as int32/float32 can't be all {0,1}/{0.0f,1.0f}).
__global__ void deg_kernel(const int* __restrict__ row,
                           const float* __restrict__ w, int E,
                           const void* mask) {
    if (blockIdx.x == 0 && threadIdx.x == 0) {
        const int*   mi = (const int*)mask;
        const float* mf = (const float*)mask;
        bool isInt = true, isFloat = true;
        for (int k = 0; k < 64; k++) {
            int v = mi[k];
            if (v != 0 && v != 1) isInt = false;
            float f = mf[k];
            if (f != 0.0f && f != 1.0f) isFloat = false;
        }
        g_maskmode = isInt ? 2 : (isFloat ? 1 : 0);
    }
    int nvec   = E >> 2;
    int stride = gridDim.x * blockDim.x;
    for (int i = blockIdx.x * blockDim.x + threadIdx.x; i < nvec; i += stride) {
        int4   r4 = ((const int4*)row)[i];
        float4 w4 = ((const float4*)w)[i];
        atomicAdd(&g_deg[r4.x], w4.x);
        atomicAdd(&g_deg[r4.y], w4.y);
        atomicAdd(&g_deg[r4.z], w4.z);
        atomicAdd(&g_deg[r4.w], w4.w);
    }
    if (blockIdx.x == 0 && threadIdx.x < (E & 3)) {
        int e = (E & ~3) + threadIdx.x;
        atomicAdd(&g_deg[row[e]], w[e]);
    }
}

// 4 threads/node. Masked: label + cnt + diag(dinv^2); skip softmax & p store.
// Unmasked: softmax -> p store; skip y load. Always: zero this node's s row,
// write info, reset g_deg[node]=0 (maintains the invariant for next replay).
__global__ void node_kernel(const float* __restrict__ inp,
                            const float* __restrict__ y,
                            const void* mask, int N) {
    int tid  = blockIdx.x * blockDim.x + threadIdx.x;
    int node = tid >> 2;
    int sub  = tid & 3;
    if (node >= N) return;
    unsigned gm = 0xFu << (threadIdx.x & 28);   // 4-lane aligned group mask
    int mm = g_maskmode;
    bool mk = get_mask(mask, node, mm);

    int labl = -1;
    if (mk) {
        const float4* yp = (const float4*)(y + node * CC) + sub * 2;
        float4 ya = yp[0], yb = yp[1];
        int bse = sub * 8;
        if (ya.x > 0.5f) labl = bse + 0;
        if (ya.y > 0.5f) labl = bse + 1;
        if (ya.z > 0.5f) labl = bse + 2;
        if (ya.w > 0.5f) labl = bse + 3;
        if (yb.x > 0.5f) labl = bse + 4;
        if (yb.y > 0.5f) labl = bse + 5;
        if (yb.z > 0.5f) labl = bse + 6;
        if (yb.w > 0.5f) labl = bse + 7;
        labl = max(labl, __shfl_xor_sync(gm, labl, 1));
        labl = max(labl, __shfl_xor_sync(gm, labl, 2));
    } else {
        const float4* ip = (const float4*)(inp + node * CC) + sub * 2;
        float4 a = ip[0], b = ip[1];
        float mx = fmaxf(fmaxf(fmaxf(a.x, a.y), fmaxf(a.z, a.w)),
                         fmaxf(fmaxf(b.x, b.y), fmaxf(b.z, b.w)));
        mx = fmaxf(mx, __shfl_xor_sync(gm, mx, 1));
        mx = fmaxf(mx, __shfl_xor_sync(gm, mx, 2));
        float e0 = __expf(a.x - mx), e1 = __expf(a.y - mx),
              e2 = __expf(a.z - mx), e3 = __expf(a.w - mx),
              e4 = __expf(b.x - mx), e5 = __expf(b.y - mx),
              e6 = __expf(b.z - mx), e7 = __expf(b.w - mx);
        float s = ((e0 + e1) + (e2 + e3)) + ((e4 + e5) + (e6 + e7));
        s += __shfl_xor_sync(gm, s, 1);
        s += __shfl_xor_sync(gm, s, 2);
        float inv = __frcp_rn(s);
        float4* op = (float4*)(g_p + node * CC) + sub * 2;
        op[0] = make_float4(e0 * inv, e1 * inv, e2 * inv, e3 * inv);
        op[1] = make_float4(e4 * inv, e5 * inv, e6 * inv, e7 * inv);
    }

    // reset s row (scatter accumulates into it next)
    float4 z = make_float4(0.f, 0.f, 0.f, 0.f);
    float4* sp = (float4*)(g_s + node * CC) + sub * 2;
    sp[0] = z; sp[1] = z;

    if (sub == 0) {
        float d  = g_deg[node];
        g_deg[node] = 0.0f;                 // maintain invariant for next call
        float di = rsqrtf(1.0f + d);        // self-loop weight 1 included
        g_info[node] = make_int2(__float_as_int(di), mk ? labl : -1);
        if (mk) {
            atomicAdd(&g_cnt[labl], 1.0f);
            atomicAdd(&g_diag[labl], di * di);  // masked self-loop -> H[l][l]
        }
    }
}

// Edge scatter, mask-split. For masked-row edges, v = dinv_r * w * dinv_c:
//   col masked   -> scalar into per-block smem H tile [lab_r][lab_c]
//   col unmasked -> global atomic into s[col][lab_r]
__global__ void scatter_kernel(const int* __restrict__ row,
                               const int* __restrict__ col,
                               const float* __restrict__ w, int E) {
    __shared__ float sH[CC * 33];
    for (int k = threadIdx.x; k < CC * 33; k += blockDim.x) sH[k] = 0.0f;
    __syncthreads();

    int nvec   = E >> 2;
    int stride = gridDim.x * blockDim.x;
    for (int i = blockIdx.x * blockDim.x + threadIdx.x; i < nvec; i += stride) {
        int4   r4 = ((const int4*)row)[i];
        int4   c4 = ((const int4*)col)[i];
        float4 w4 = ((const float4*)w)[i];
        int2 i0 = g_info[r4.x];
        int2 i1 = g_info[r4.y];
        int2 i2 = g_info[r4.z];
        int2 i3 = g_info[r4.w];
        if (i0.y >= 0) {
            int2 ic = g_info[c4.x];
            float v = __int_as_float(i0.x) * w4.x * __int_as_float(ic.x);
            if (ic.y >= 0) atomicAdd(&sH[i0.y * 33 + ic.y], v);
            else           atomicAdd(&g_s[c4.x * CC + i0.y], v);
        }
        if (i1.y >= 0) {
            int2 ic = g_info[c4.y];
            float v = __int_as_float(i1.x) * w4.y * __int_as_float(ic.x);
            if (ic.y >= 0) atomicAdd(&sH[i1.y * 33 + ic.y], v);
            else           atomicAdd(&g_s[c4.y * CC + i1.y], v);
        }
        if (i2.y >= 0) {
            int2 ic = g_info[c4.z];
            float v = __int_as_float(i2.x) * w4.z * __int_as_float(ic.x);
            if (ic.y >= 0) atomicAdd(&sH[i2.y * 33 + ic.y], v);
            else           atomicAdd(&g_s[c4.z * CC + i2.y], v);
        }
        if (i3.y >= 0) {
            int2 ic = g_info[c4.w];
            float v = __int_as_float(i3.x) * w4.w * __int_as_float(ic.x);
            if (ic.y >= 0) atomicAdd(&sH[i3.y * 33 + ic.y], v);
            else           atomicAdd(&g_s[c4.w * CC + i3.y], v);
        }
    }
    if (blockIdx.x == 0 && threadIdx.x < (E & 3)) {
        int e = (E & ~3) + threadIdx.x;
        int r = row[e], c = col[e];
        int2 ir = g_info[r];
        if (ir.y >= 0) {
            int2 ic = g_info[c];
            float v = __int_as_float(ir.x) * w[e] * __int_as_float(ic.x);
            if (ic.y >= 0) atomicAdd(&sH[ir.y * 33 + ic.y], v);
            else           atomicAdd(&g_s[c * CC + ir.y], v);
        }
    }
    __syncthreads();
    for (int k = threadIdx.x; k < CC * CC; k += blockDim.x) {
        float v = sH[(k >> 5) * 33 + (k & 31)];
        if (v != 0.0f) atomicAdd(&g_H[k], v);
    }
}

// Dense rank-1 sum over UNMASKED nodes (s==0 elsewhere, ballot-skipped):
// H[a][j] += sum_c s[c][a] * p[c][j]. One warp per node, grid-strided.
__global__ void dense_kernel(int N) {
    int wid  = threadIdx.x >> 5;
    int lane = threadIdx.x & 31;
    int gw     = blockIdx.x * 8 + wid;
    int stride = gridDim.x * 8;

    float acc[CC];
    #pragma unroll
    for (int a = 0; a < CC; a++) acc[a] = 0.0f;

    for (int c = gw; c < N; c += stride) {
        float sv = g_s[c * CC + lane];
        if (__ballot_sync(0xffffffffu, sv != 0.0f) == 0) continue;
        float pv = g_p[c * CC + lane];
        #pragma unroll
        for (int a = 0; a < CC; a++)
            acc[a] += __shfl_sync(0xffffffffu, sv, a) * pv;
    }
    #pragma unroll
    for (int a = 0; a < CC; a++)
        atomicAdd(&g_H[a * CC + lane], acc[a]);
}

// Final: H = (acc + diag)/cnt, NaN fixups, Sinkhorn to convergence (fixed
// point of the reference's 3000 iterations). Also resets accumulators.
__global__ void final_kernel(float* __restrict__ out) {
    __shared__ float sm[CC * 33];
    __shared__ float sred[CC];
    __shared__ int   sflag;

    int i = threadIdx.x >> 5;   // row
    int j = threadIdx.x & 31;   // col (lane)

    float acc = g_H[i * CC + j];
    if (i == j) acc += g_diag[i];
    float cnt = g_cnt[i];

    // reset accumulators for the next replay (each thread owns its cell)
    g_H[i * CC + j] = 0.0f;
    if (j == 0) { g_cnt[i] = 0.0f; g_diag[i] = 0.0f; }

    float h = acc / cnt;        // 0/0 -> NaN if empty class

    // Fixup 1: H = where(isnan(H), H^T, H)
    sm[j * 33 + i] = h;
    __syncthreads();
    float ht = sm[i * 33 + j];
    if (isnan(h)) h = ht;
    __syncthreads();

    // Fixup 2
    bool n2 = isnan(h);
    float h0 = n2 ? 0.0f : h;
    float rs = h0;
    float rn = n2 ? 1.0f : 0.0f;
    #pragma unroll
    for (int o = 16; o; o >>= 1) {
        rs += __shfl_xor_sync(0xffffffffu, rs, o);
        rn += __shfl_xor_sync(0xffffffffu, rn, o);
    }
    float miss = (1.0f - rs) / rn;
    h = n2 ? miss : h0;

    // Sinkhorn: col-normalize then row-normalize until converged (cap 3000)
    float hsave = h;
    for (int it = 0; it < 3000; it++) {
        sm[i * 33 + j] = h;
        __syncthreads();
        float vc = sm[j * 33 + i];
        float cs = vc;
        #pragma unroll
        for (int o = 16; o; o >>= 1) cs += __shfl_xor_sync(0xffffffffu, cs, o);
        vc /= cs;
        sm[j * 33 + i] = vc;
        __syncthreads();
        h = sm[i * 33 + j];
        float rs2 = h;
        #pragma unroll
        for (int o = 16; o; o >>= 1) rs2 += __shfl_xor_sync(0xffffffffu, rs2, o);
        h /= rs2;

        if ((it & 7) == 7) {
            float d = fabsf(h - hsave);
            #pragma unroll
            for (int o = 16; o; o >>= 1) d = fmaxf(d, __shfl_xor_sync(0xffffffffu, d, o));
            if (j == 0) sred[i] = d;
            __syncthreads();
            if (threadIdx.x == 0) {
                float m = 0.0f;
                for (int k = 0; k < CC; k++) m = fmaxf(m, sred[k]);
                sflag = (m < 1e-8f) ? 1 : 0;
            }
            __syncthreads();
            if (sflag) break;
            hsave = h;
        }
    }
    out[i * CC + j] = h;
}

// ---------------------------------------------------------------------------
extern "C" void kernel_launch(void* const* d_in, const int* in_sizes, int n_in,
                              void* d_out, int out_size) {
    const int*   ei   = (const int*)d_in[0];    // edge_index (2,E)
    const float* ew   = (const float*)d_in[1];  // edge_weight (E,)
    const float* inp  = (const float*)d_in[2];  // inputs (N,32)
    const float* y    = (const float*)d_in[3];  // y (N,32)
    const void*  mask = d_in[4];                // sample_mask (N,)

    int E = in_sizes[1];
    int N = in_sizes[2] / CC;
    const int* rowp = ei;
    const int* colp = ei + E;

    deg_kernel<<<1184, 256>>>(rowp, ew, E, mask);
    node_kernel<<<(N * 4 + 255) / 256, 256>>>(inp, y, mask, N);
    scatter_kernel<<<888, 256>>>(rowp, colp, ew, E);
    dense_kernel<<<592, 256>>>(N);
    final_kernel<<<1, 1024>>>((float*)d_out);
}

// round 5
// speedup vs baseline: 1.0262x; 1.0262x over previous
#include <cuda_runtime.h>
#include <stdint.h>
#include <math.h>

// Problem dims (dataset): N=100000 nodes, C=32 classes, E=3.2M edges
#define NMAX 100000
#define CC 32

// Scratch (device globals, zero-initialized at load; all state is
// self-resetting so repeated graph replays are deterministic).
__device__ float g_s[NMAX * CC];      // scatter matrix; ==0 at entry (dense resets rows it uses)
__device__ int2  g_info[NMAX];        // .x = bitcast(dinv), .y = label (-1 unmasked)
__device__ float g_deg[NMAX];         // ==0 at entry (node resets)
__device__ float g_H[CC * CC];        // ==0 at entry (final resets)
__device__ float g_cnt[CC];           // ==0 at entry
__device__ float g_diag[CC];          // ==0 at entry; masked self-loop dinv^2 per class
__device__ int   g_done;              // ==0 at entry; dense block ticket
__device__ int   g_maskmode;          // 0=uint8, 1=float32, 2=int32

__device__ __forceinline__ bool get_mask(const void* m, int r, int mm) {
    if (mm == 0) return ((const uint8_t*)m)[r] != 0;
    if (mm == 2) return ((const int*)m)[r] != 0;
    return ((const float*)m)[r] != 0.0f;
}

// ---------------------------------------------------------------------------
// deg += segment_sum(w, row); self-loop "+1" applied analytically later.
// Block 0 detects mask dtype (byte-mask viewed as int32/float32 can't be all
// {0,1}/{0.0f,1.0f}).
__global__ void deg_kernel(const int* __restrict__ row,
                           const float* __restrict__ w, int E,
                           const void* mask) {
    if (blockIdx.x == 0 && threadIdx.x == 0) {
        const int*   mi = (const int*)mask;
        const float* mf = (const float*)mask;
        bool isInt = true, isFloat = true;
        for (int k = 0; k < 64; k++) {
            int v = mi[k];
            if (v != 0 && v != 1) isInt = false;
            float f = mf[k];
            if (f != 0.0f && f != 1.0f) isFloat = false;
        }
        g_maskmode = isInt ? 2 : (isFloat ? 1 : 0);
    }
    int nvec   = E >> 2;
    int stride = gridDim.x * blockDim.x;
    for (int i = blockIdx.x * blockDim.x + threadIdx.x; i < nvec; i += stride) {
        int4   r4 = ((const int4*)row)[i];
        float4 w4 = ((const float4*)w)[i];
        atomicAdd(&g_deg[r4.x], w4.x);
        atomicAdd(&g_deg[r4.y], w4.y);
        atomicAdd(&g_deg[r4.z], w4.z);
        atomicAdd(&g_deg[r4.w], w4.w);
    }
    if (blockIdx.x == 0 && threadIdx.x < (E & 3)) {
        int e = (E & ~3) + threadIdx.x;
        atomicAdd(&g_deg[row[e]], w[e]);
    }
}

// 4 threads/node. Masked: label from y + cnt + diag(dinv^2). All: write info,
// reset g_deg[node]=0 (maintains invariant for next replay). No softmax here —
// dense computes it on the fly. No s zeroing — dense self-cleans.
__global__ void node_kernel(const float* __restrict__ y,
                            const void* mask, int N) {
    int tid  = blockIdx.x * blockDim.x + threadIdx.x;
    int node = tid >> 2;
    int sub  = tid & 3;
    if (node >= N) return;
    unsigned gm = 0xFu << (threadIdx.x & 28);   // 4-lane aligned group mask
    bool mk = get_mask(mask, node, g_maskmode);

    int labl = -1;
    if (mk) {
        const float4* yp = (const float4*)(y + node * CC) + sub * 2;
        float4 ya = yp[0], yb = yp[1];
        int bse = sub * 8;
        if (ya.x > 0.5f) labl = bse + 0;
        if (ya.y > 0.5f) labl = bse + 1;
        if (ya.z > 0.5f) labl = bse + 2;
        if (ya.w > 0.5f) labl = bse + 3;
        if (yb.x > 0.5f) labl = bse + 4;
        if (yb.y > 0.5f) labl = bse + 5;
        if (yb.z > 0.5f) labl = bse + 6;
        if (yb.w > 0.5f) labl = bse + 7;
        labl = max(labl, __shfl_xor_sync(gm, labl, 1));
        labl = max(labl, __shfl_xor_sync(gm, labl, 2));
    }

    if (sub == 0) {
        float d  = g_deg[node];
        g_deg[node] = 0.0f;                 // invariant for next call
        float di = rsqrtf(1.0f + d);        // self-loop weight 1 included
        g_info[node] = make_int2(__float_as_int(di), mk ? labl : -1);
        if (mk) {
            atomicAdd(&g_cnt[labl], 1.0f);
            atomicAdd(&g_diag[labl], di * di);  // masked self-loop -> H[l][l]
        }
    }
}

// Edge scatter, mask-split. For masked-row edges, v = dinv_r * w * dinv_c:
//   col masked   -> scalar into per-block smem H tile [lab_r][lab_c]
//   col unmasked -> global atomic into s[col][lab_r]
__global__ void scatter_kernel(const int* __restrict__ row,
                               const int* __restrict__ col,
                               const float* __restrict__ w, int E) {
    __shared__ float sH[CC * 33];
    for (int k = threadIdx.x; k < CC * 33; k += blockDim.x) sH[k] = 0.0f;
    __syncthreads();

    int nvec   = E >> 2;
    int stride = gridDim.x * blockDim.x;
    for (int i = blockIdx.x * blockDim.x + threadIdx.x; i < nvec; i += stride) {
        int4   r4 = ((const int4*)row)[i];
        int4   c4 = ((const int4*)col)[i];
        float4 w4 = ((const float4*)w)[i];
        int2 i0 = g_info[r4.x];
        int2 i1 = g_info[r4.y];
        int2 i2 = g_info[r4.z];
        int2 i3 = g_info[r4.w];
        if (i0.y >= 0) {
            int2 ic = g_info[c4.x];
            float v = __int_as_float(i0.x) * w4.x * __int_as_float(ic.x);
            if (ic.y >= 0) atomicAdd(&sH[i0.y * 33 + ic.y], v);
            else           atomicAdd(&g_s[c4.x * CC + i0.y], v);
        }
        if (i1.y >= 0) {
            int2 ic = g_info[c4.y];
            float v = __int_as_float(i1.x) * w4.y * __int_as_float(ic.x);
            if (ic.y >= 0) atomicAdd(&sH[i1.y * 33 + ic.y], v);
            else           atomicAdd(&g_s[c4.y * CC + i1.y], v);
        }
        if (i2.y >= 0) {
            int2 ic = g_info[c4.z];
            float v = __int_as_float(i2.x) * w4.z * __int_as_float(ic.x);
            if (ic.y >= 0) atomicAdd(&sH[i2.y * 33 + ic.y], v);
            else           atomicAdd(&g_s[c4.z * CC + i2.y], v);
        }
        if (i3.y >= 0) {
            int2 ic = g_info[c4.w];
            float v = __int_as_float(i3.x) * w4.w * __int_as_float(ic.x);
            if (ic.y >= 0) atomicAdd(&sH[i3.y * 33 + ic.y], v);
            else           atomicAdd(&g_s[c4.w * CC + i3.y], v);
        }
    }
    if (blockIdx.x == 0 && threadIdx.x < (E & 3)) {
        int e = (E & ~3) + threadIdx.x;
        int r = row[e], c = col[e];
        int2 ir = g_info[r];
        if (ir.y >= 0) {
            int2 ic = g_info[c];
            float v = __int_as_float(ir.x) * w[e] * __int_as_float(ic.x);
            if (ic.y >= 0) atomicAdd(&sH[ir.y * 33 + ic.y], v);
            else           atomicAdd(&g_s[c * CC + ir.y], v);
        }
    }
    __syncthreads();
    for (int k = threadIdx.x; k < CC * CC; k += blockDim.x) {
        float v = sH[(k >> 5) * 33 + (k & 31)];
        if (v != 0.0f) atomicAdd(&g_H[k], v);
    }
}

// Dense rank-1 sum + fused final. Warp per row, 8-row batches (MLP=8).
// Softmax computed on the fly from inputs (rows with s!=0 are unmasked).
// s rows are zeroed after use. Last block runs NaN fixups + Sinkhorn.
__global__ void __launch_bounds__(1024, 1)
dense_final_kernel(const float* __restrict__ inp, int N,
                   float* __restrict__ out) {
    int wid  = threadIdx.x >> 5;
    int lane = threadIdx.x & 31;
    int gw     = blockIdx.x * 32 + wid;
    int nwarps = gridDim.x * 32;

    float acc[CC];
    #pragma unroll
    for (int a = 0; a < CC; a++) acc[a] = 0.0f;

    for (int base = gw * 8; base < N; base += nwarps * 8) {
        float sv[8];
        #pragma unroll
        for (int k = 0; k < 8; k++) {
            int c = base + k;
            sv[k] = (c < N) ? g_s[c * CC + lane] : 0.0f;   // 8 loads in flight
        }
        #pragma unroll
        for (int k = 0; k < 8; k++) {
            if (__ballot_sync(0xffffffffu, sv[k] != 0.0f)) {
                int c = base + k;
                float x = inp[c * CC + lane];
                float mx = x;
                #pragma unroll
                for (int o = 16; o; o >>= 1)
                    mx = fmaxf(mx, __shfl_xor_sync(0xffffffffu, mx, o));
                float e = __expf(x - mx);
                float s = e;
                #pragma unroll
                for (int o = 16; o; o >>= 1)
                    s += __shfl_xor_sync(0xffffffffu, s, o);
                float pv = e * __frcp_rn(s);
                #pragma unroll
                for (int a = 0; a < CC; a++)
                    acc[a] += __shfl_sync(0xffffffffu, sv[k], a) * pv;
                g_s[c * CC + lane] = 0.0f;     // self-clean for next replay
            }
        }
    }
    #pragma unroll
    for (int a = 0; a < CC; a++)
        atomicAdd(&g_H[a * CC + lane], acc[a]);

    // ---- last-block-done: run the final reduction with this block ----
    __shared__ int sticket;
    __threadfence();
    __syncthreads();
    if (threadIdx.x == 0) sticket = atomicAdd(&g_done, 1);
    __syncthreads();
    if (sticket != gridDim.x - 1) return;

    __shared__ float sm[CC * 33];
    __shared__ float sred[CC];
    __shared__ int   sflag;

    int i = threadIdx.x >> 5;   // row
    int j = threadIdx.x & 31;   // col

    float a2 = __ldcg(&g_H[i * CC + j]);       // L2-coherent read past atomics
    if (i == j) a2 += __ldcg(&g_diag[i]);
    float cnt = __ldcg(&g_cnt[i]);

    // reset accumulators for the next replay
    g_H[i * CC + j] = 0.0f;
    if (j == 0) { g_cnt[i] = 0.0f; g_diag[i] = 0.0f; }
    if (threadIdx.x == 0) g_done = 0;

    float h = a2 / cnt;         // 0/0 -> NaN if empty class

    // Fixup 1: H = where(isnan(H), H^T, H)
    sm[j * 33 + i] = h;
    __syncthreads();
    float ht = sm[i * 33 + j];
    if (isnan(h)) h = ht;
    __syncthreads();

    // Fixup 2
    bool n2 = isnan(h);
    float h0 = n2 ? 0.0f : h;
    float rs = h0;
    float rn = n2 ? 1.0f : 0.0f;
    #pragma unroll
    for (int o = 16; o; o >>= 1) {
        rs += __shfl_xor_sync(0xffffffffu, rs, o);
        rn += __shfl_xor_sync(0xffffffffu, rn, o);
    }
    float miss = (1.0f - rs) / rn;
    h = n2 ? miss : h0;

    // Sinkhorn: col-normalize then row-normalize until converged (cap 3000;
    // fixed point of the reference's 3000 iterations)
    float hsave = h;
    for (int it = 0; it < 3000; it++) {
        sm[i * 33 + j] = h;
        __syncthreads();
        float vc = sm[j * 33 + i];
        float cs = vc;
        #pragma unroll
        for (int o = 16; o; o >>= 1) cs += __shfl_xor_sync(0xffffffffu, cs, o);
        vc /= cs;
        sm[j * 33 + i] = vc;
        __syncthreads();
        h = sm[i * 33 + j];
        float rs2 = h;
        #pragma unroll
        for (int o = 16; o; o >>= 1) rs2 += __shfl_xor_sync(0xffffffffu, rs2, o);
        h /= rs2;

        if ((it & 7) == 7) {
            float d = fabsf(h - hsave);
            #pragma unroll
            for (int o = 16; o; o >>= 1) d = fmaxf(d, __shfl_xor_sync(0xffffffffu, d, o));
            if (j == 0) sred[i] = d;
            __syncthreads();
            if (threadIdx.x == 0) {
                float m = 0.0f;
                for (int k = 0; k < CC; k++) m = fmaxf(m, sred[k]);
                sflag = (m < 1e-8f) ? 1 : 0;
            }
            __syncthreads();
            if (sflag) break;
            hsave = h;
        }
    }
    out[i * CC + j] = h;
}

// ---------------------------------------------------------------------------
extern "C" void kernel_launch(void* const* d_in, const int* in_sizes, int n_in,
                              void* d_out, int out_size) {
    const int*   ei   = (const int*)d_in[0];    // edge_index (2,E)
    const float* ew   = (const float*)d_in[1];  // edge_weight (E,)
    const float* inp  = (const float*)d_in[2];  // inputs (N,32)
    const float* y    = (const float*)d_in[3];  // y (N,32)
    const void*  mask = d_in[4];                // sample_mask (N,)

    int E = in_sizes[1];
    int N = in_sizes[2] / CC;
    const int* rowp = ei;
    const int* colp = ei + E;

    deg_kernel<<<1184, 256>>>(rowp, ew, E, mask);
    node_kernel<<<(N * 4 + 255) / 256, 256>>>(y, mask, N);
    scatter_kernel<<<888, 256>>>(rowp, colp, ew, E);
    dense_final_kernel<<<148, 1024>>>(inp, N, (float*)d_out);
}